// round 8
// baseline (speedup 1.0000x reference)
#include <cuda_runtime.h>

// ---------------------------------------------------------------------------
// PatchTokenizer: single fused kernel.
//   blocks 0..31      : per-batch masks + stitch + sel finalize + output_mask
//   blocks 32..13855  : gather sections (spin on g_go until sel ready)
// Output layout (all float32, tuple order of the reference) -- see OFFs.
// ---------------------------------------------------------------------------

#define OFF1 25165824
#define OFF2 31457280
#define OFF3 33030144
#define OFF4 58195968
#define OFF5 83361792
#define OFF6 83394560
#define OFF7 83402752
#define OFF8 83404800
#define OFF9 83404803
#define OFF10 83447843
#define OFF11 83447875
#define OFF12 83447908
#define OFF13 83447909

// scratch (allocation-free rule: __device__ globals; all counters self-reset)
__device__ int g_c0[32], g_c1[32], g_c2[32];
__device__ int g_sel0[32768], g_sel1[8192], g_sel2[2048];
__device__ int g_cnt[3];
__device__ int g_ready, g_fin, g_go, g_done;

__device__ __forceinline__ float4 zero4() { return make_float4(0.f, 0.f, 0.f, 0.f); }

// big-section block ranges (after subtracting the 32 mask blocks)
#define NB0 3072
#define NB1 3072
#define NB2 1536
#define NB3 3072
#define NB4 3072
#define E0 (NB0)
#define E1 (NB0 + NB1)
#define E2 (NB0 + NB1 + NB2)
#define E3 (NB0 + NB1 + NB2 + NB3)
#define E4 (NB0 + NB1 + NB2 + NB3 + NB4)   // 13824
#define NBLK (32 + E4)                      // 13856

__global__ void __launch_bounds__(256)
fused_kernel(const float* __restrict__ img,
             const float* __restrict__ imp1, const float* __restrict__ imp2,
             float* __restrict__ out) {
    const int bs = blockIdx.x;
    const int tid = threadIdx.x;

    if (bs < 32) {
        // ================= MASK BLOCK (batch b = bs) ======================
        const int b = bs;
        __shared__ unsigned char sm2[64], sm1[256];
        __shared__ unsigned short ssel0[1024], ssel1[256], ssel2[64];
        __shared__ int w0[8], w1[8], w2[8];
        __shared__ int sOff0, sOff1, sOff2;
        __shared__ int s_scu[33], s_sc0[32], s_sc01[32];

        // ---- phase 1: per-batch masks ------------------------------------
        unsigned char v2 = 0;
        if (tid < 64) {
            v2 = imp2[b * 64 + tid] < 0.3f;
            sm2[tid] = v2;
            out[OFF7 + b * 64 + tid] = (float)v2;
        }
        __syncthreads();

        unsigned char v1;
        {
            int r = tid >> 4, c = tid & 15;
            unsigned char cov2 = sm2[((r >> 1) << 3) + (c >> 1)];
            v1 = (imp1[b * 256 + tid] < 0.5f) && !cov2;
            sm1[tid] = v1;
            out[OFF6 + b * 256 + tid] = (float)v1;
        }
        __syncthreads();

        unsigned char v0[4];
#pragma unroll
        for (int k = 0; k < 4; k++) {
            int j = tid * 4 + k;
            int r = j >> 5, c = j & 31;
            unsigned char cov = sm2[((r >> 2) << 3) + (c >> 2)] |
                                sm1[((r >> 1) << 4) + (c >> 1)];
            v0[k] = !cov;
            out[OFF5 + b * 1024 + j] = (float)v0[k];
        }

        // ---- local compaction scans -> shared sel lists -------------------
        const int lane = tid & 31, wid = tid >> 5;
        int s0 = v0[0] + v0[1] + v0[2] + v0[3];
        int a1 = (int)v1, a2 = (tid < 64) ? (int)v2 : 0;
        int i0 = s0, i1 = a1, i2 = a2;
#pragma unroll
        for (int o = 1; o < 32; o <<= 1) {
            int n0 = __shfl_up_sync(0xffffffffu, i0, o);
            int n1 = __shfl_up_sync(0xffffffffu, i1, o);
            int n2 = __shfl_up_sync(0xffffffffu, i2, o);
            if (lane >= o) { i0 += n0; i1 += n1; i2 += n2; }
        }
        if (lane == 31) { w0[wid] = i0; w1[wid] = i1; w2[wid] = i2; }
        __syncthreads();
        int base0 = 0, base1 = 0, base2 = 0, tot0 = 0, tot1 = 0, tot2 = 0;
#pragma unroll
        for (int k = 0; k < 8; k++) {
            if (k < wid) { base0 += w0[k]; base1 += w1[k]; base2 += w2[k]; }
            tot0 += w0[k]; tot1 += w1[k]; tot2 += w2[k];
        }
        {
            int r = base0 + i0 - s0;
#pragma unroll
            for (int k = 0; k < 4; k++)
                if (v0[k]) ssel0[r++] = (unsigned short)(tid * 4 + k);
        }
        if (v1) ssel1[base1 + i1 - a1] = (unsigned short)tid;
        if (tid < 64 && v2) ssel2[base2 + i2 - a2] = (unsigned short)tid;

        if (tid == 0) {
            g_c0[b] = tot0; g_c1[b] = tot1; g_c2[b] = tot2;
            out[OFF10 + b] = (float)(1 + tot0 + tot1 + tot2);
        }
        __threadfence();
        __syncthreads();
        if (tid == 0) {
            atomicAdd(&g_ready, 1);
            while (atomicAdd(&g_ready, 0) < 32) { __nanosleep(64); }
            __threadfence();
        }
        __syncthreads();
        __threadfence();

        // ---- distributed stitch ------------------------------------------
        if (tid < 32) {
            int c0 = g_c0[tid], c1 = g_c1[tid], c2 = g_c2[tid];
            int sl = 1 + c0 + c1 + c2;
            int x0 = c0, x1 = c1, x2 = c2, xs = sl;
#pragma unroll
            for (int o = 1; o < 32; o <<= 1) {
                int n0 = __shfl_up_sync(0xffffffffu, x0, o);
                int n1 = __shfl_up_sync(0xffffffffu, x1, o);
                int n2 = __shfl_up_sync(0xffffffffu, x2, o);
                int ns = __shfl_up_sync(0xffffffffu, xs, o);
                if (tid >= o) { x0 += n0; x1 += n1; x2 += n2; xs += ns; }
            }
            if (tid == b) { sOff0 = x0 - c0; sOff1 = x1 - c1; sOff2 = x2 - c2; }
            s_scu[tid + 1] = xs;
            s_sc0[tid] = c0;
            s_sc01[tid] = c0 + c1;
            if (tid == 0) s_scu[0] = 0;
            if (b == 0) {
                out[OFF11 + 1 + tid] = (float)xs;
                int mx = sl;
#pragma unroll
                for (int o = 16; o; o >>= 1) {
                    int n = __shfl_xor_sync(0xffffffffu, mx, o);
                    mx = mx > n ? mx : n;
                }
                if (tid == 0) {
                    out[OFF11] = 0.0f;
                    out[OFF12] = (float)mx;
                }
                if (tid == 31) {
                    g_cnt[0] = x0; g_cnt[1] = x1; g_cnt[2] = x2;
                    out[OFF8 + 0] = (float)x0;
                    out[OFF8 + 1] = (float)x1;
                    out[OFF8 + 2] = (float)x2;
                    out[OFF13] = (float)xs / 32768.0f;
                }
            }
        }
        __syncthreads();

        // ---- finalize this batch's global sel entries --------------------
        for (int r = tid; r < tot0; r += 256)
            g_sel0[sOff0 + r] = (int)ssel0[r] + (b << 10);
        for (int r = tid; r < tot1; r += 256)
            g_sel1[sOff1 + r] = (int)ssel1[r] + (b << 8);
        for (int r = tid; r < tot2; r += 256)
            g_sel2[sOff2 + r] = (int)ssel2[r] + (b << 6);

        __threadfence();
        __syncthreads();
        if (tid == 0) {
            int f = atomicAdd(&g_fin, 1);
            if (f == 31) {
                __threadfence();
                *(volatile int*)&g_go = 1;
            }
        }

        // ---- this block's slice of compacted output_mask -----------------
        const int tot = s_scu[32];
        for (int j = b * 1345 + tid; j < (b + 1) * 1345; j += 256) {
            float v = 0.0f;
            if (j < tot) {
                int bb = 0;
                while (s_scu[bb + 1] <= j) bb++;
                int r = j - s_scu[bb];
                if (r == 0) v = -1.0f;
                else {
                    r -= 1;
                    if (r < s_sc0[bb]) v = 1.0f;
                    else if (r < s_sc01[bb]) v = 2.0f;
                    else v = 3.0f;
                }
            }
            out[OFF9 + j] = v;
        }
    } else {
        // ================= GATHER BLOCK ====================================
        if (tid == 0) {
            while (*(volatile int*)&g_go == 0) { __nanosleep(128); }
            __threadfence();
        }
        __syncthreads();

        const int gs = bs - 32;

        if (gs < E0) {
            // ---- S0: resized0 (pure copy of 16x16 base patches) ----------
            const int cnt = g_cnt[0];
            const int base = gs * 2048 + tid;
            int off[8];
#pragma unroll
            for (int k = 0; k < 8; k++) {
                int i = base + k * 256;
                int p = i / 192, t4 = i - p * 192;
                if (p < cnt) {
                    int s = g_sel0[p];
                    int b = s >> 10, gy = (s >> 5) & 31, gx = s & 31;
                    int e = t4 << 2;
                    int c = e >> 8, y = (e >> 4) & 15, x = e & 15;
                    off[k] = ((b * 3 + c) * 512 + gy * 16 + y) * 512 + gx * 16 + x;
                } else off[k] = -1;
            }
            float4 v[8];
#pragma unroll
            for (int k = 0; k < 8; k++)
                v[k] = (off[k] >= 0) ? *reinterpret_cast<const float4*>(img + off[k]) : zero4();
            float4* dst = reinterpret_cast<float4*>(out);
#pragma unroll
            for (int k = 0; k < 8; k++) dst[base + k * 256] = v[k];

        } else if (gs < E1) {
            // ---- S1: resized1 (2x2 average of original) -------------------
            const int cnt = g_cnt[1];
            const int base = (gs - E0) * 512 + tid;
            int off[2];
#pragma unroll
            for (int k = 0; k < 2; k++) {
                int i = base + k * 256;
                int p = i / 192, t4 = i - p * 192;
                if (p < cnt) {
                    int s = g_sel1[p];
                    int b = s >> 8, gy = (s >> 4) & 15, gx = s & 15;
                    int e = t4 << 2;
                    int c = e >> 8, y = (e >> 4) & 15, x = e & 15;
                    int R = gy * 32 + 2 * y, Cc = gx * 32 + 2 * x;
                    off[k] = ((b * 3 + c) * 512 + R) * 512 + Cc;
                } else off[k] = -1;
            }
            float4 a0[2], a1[2], b0[2], b1[2];
#pragma unroll
            for (int k = 0; k < 2; k++) {
                if (off[k] >= 0) {
                    const float* bp = img + off[k];
                    a0[k] = *(const float4*)(bp);
                    a1[k] = *(const float4*)(bp + 4);
                    b0[k] = *(const float4*)(bp + 512);
                    b1[k] = *(const float4*)(bp + 516);
                }
            }
            float4* dst = reinterpret_cast<float4*>(out + OFF1);
#pragma unroll
            for (int k = 0; k < 2; k++) {
                float4 o = zero4();
                if (off[k] >= 0) {
                    o.x = (a0[k].x + a0[k].y + b0[k].x + b0[k].y) * 0.25f;
                    o.y = (a0[k].z + a0[k].w + b0[k].z + b0[k].w) * 0.25f;
                    o.z = (a1[k].x + a1[k].y + b1[k].x + b1[k].y) * 0.25f;
                    o.w = (a1[k].z + a1[k].w + b1[k].z + b1[k].w) * 0.25f;
                }
                dst[base + k * 256] = o;
            }

        } else if (gs < E2) {
            // ---- S2: resized2 (central 2x2 average, 4x downsample) --------
            const int cnt = g_cnt[2];
            const int i = (gs - E1) * 256 + tid;
            const int p = i / 192, t4 = i - p * 192;
            float4 o = zero4();
            if (p < cnt) {
                int s = g_sel2[p];
                int b = s >> 6, gy = (s >> 3) & 7, gx = s & 7;
                int e = t4 << 2;
                int c = e >> 8, y = (e >> 4) & 15, x = e & 15;
                int R0 = gy * 64 + 4 * y + 1;
                int Cb = gx * 64 + 4 * x;
                const float* r0 = img + ((b * 3 + c) * 512 + R0) * 512 + Cb;
                const float* r1 = r0 + 512;
                float4 q0 = *(const float4*)r0, q1 = *(const float4*)(r0 + 4);
                float4 q2 = *(const float4*)(r0 + 8), q3 = *(const float4*)(r0 + 12);
                float4 u0 = *(const float4*)r1, u1 = *(const float4*)(r1 + 4);
                float4 u2 = *(const float4*)(r1 + 8), u3 = *(const float4*)(r1 + 12);
                o.x = (q0.y + q0.z + u0.y + u0.z) * 0.25f;
                o.y = (q1.y + q1.z + u1.y + u1.z) * 0.25f;
                o.z = (q2.y + q2.z + u2.y + u2.z) * 0.25f;
                o.w = (q3.y + q3.z + u3.y + u3.z) * 0.25f;
            }
            reinterpret_cast<float4*>(out + OFF2)[i] = o;

        } else if (gs < E3) {
            // ---- S3: fulls0 (2x2 constituent base patches, pure copy) -----
            const int cnt = g_cnt[1];
            const int base = (gs - E2) * 2048 + tid;
            int off[8];
#pragma unroll
            for (int k = 0; k < 8; k++) {
                int i = base + k * 256;
                int p = i / 768, rf = i - p * 768;
                if (p < cnt) {
                    int s = g_sel1[p];
                    int b = s >> 8, gy = (s >> 4) & 15, gx = s & 15;
                    int e = rf << 2;
                    int sub = e / 768, rem = e - sub * 768;
                    int c = rem >> 8, y = (rem >> 4) & 15, x = rem & 15;
                    int ny = sub >> 1, nx = sub & 1;
                    int R = gy * 32 + ny * 16 + y, Cc = gx * 32 + nx * 16 + x;
                    off[k] = ((b * 3 + c) * 512 + R) * 512 + Cc;
                } else off[k] = -1;
            }
            float4 v[8];
#pragma unroll
            for (int k = 0; k < 8; k++)
                v[k] = (off[k] >= 0) ? *reinterpret_cast<const float4*>(img + off[k]) : zero4();
            float4* dst = reinterpret_cast<float4*>(out + OFF3);
#pragma unroll
            for (int k = 0; k < 8; k++) dst[base + k * 256] = v[k];

        } else {
            // ---- S4: fulls1 (4x4 constituent base patches, pure copy) -----
            const int cnt = g_cnt[2];
            const int base = (gs - E3) * 2048 + tid;
            int off[8];
#pragma unroll
            for (int k = 0; k < 8; k++) {
                int i = base + k * 256;
                int p = i / 3072, rf = i - p * 3072;
                if (p < cnt) {
                    int s = g_sel2[p];
                    int b = s >> 6, gy = (s >> 3) & 7, gx = s & 7;
                    int e = rf << 2;
                    int sub = e / 768, rem = e - sub * 768;
                    int c = rem >> 8, y = (rem >> 4) & 15, x = rem & 15;
                    int ny = sub >> 2, nx = sub & 3;
                    int R = gy * 64 + ny * 16 + y, Cc = gx * 64 + nx * 16 + x;
                    off[k] = ((b * 3 + c) * 512 + R) * 512 + Cc;
                } else off[k] = -1;
            }
            float4 v[8];
#pragma unroll
            for (int k = 0; k < 8; k++)
                v[k] = (off[k] >= 0) ? *reinterpret_cast<const float4*>(img + off[k]) : zero4();
            float4* dst = reinterpret_cast<float4*>(out + OFF4);
#pragma unroll
            for (int k = 0; k < 8; k++) dst[base + k * 256] = v[k];
        }
    }

    // ---- deterministic self-reset: last block clears all counters --------
    __syncthreads();
    if (tid == 0) {
        __threadfence();
        int d = atomicAdd(&g_done, 1);
        if (d == NBLK - 1) {
            g_ready = 0;
            g_fin = 0;
            *(volatile int*)&g_go = 0;
            g_done = 0;
            __threadfence();
        }
    }
}

extern "C" void kernel_launch(void* const* d_in, const int* in_sizes, int n_in,
                              void* d_out, int out_size) {
    const float* img = (const float*)d_in[0];   // images  (32,3,512,512)
    const float* i1  = (const float*)d_in[2];   // imp_s1  (32,16,16)
    const float* i2  = (const float*)d_in[3];   // imp_s2  (32,8,8)
    float* out = (float*)d_out;

    fused_kernel<<<NBLK, 256>>>(img, i1, i2, out);
}

// round 9
// speedup vs baseline: 1.1359x; 1.1359x over previous
#include <cuda_runtime.h>

// ---------------------------------------------------------------------------
// PatchTokenizer: hierarchical mask selection + compacted patch gathers.
// Two kernels:
//   mask_kernel (32 blocks): barrier-free — every block redundantly computes
//     all 32 batches' counts (c0 = 1024-16*c2-4*c1), derives global offsets
//     locally, then does its own batch's masks/compaction + output_mask slice.
//   mega_kernel (13824 blocks): the proven gather/zero-tail sections.
// ---------------------------------------------------------------------------

#define OFF1 25165824
#define OFF2 31457280
#define OFF3 33030144
#define OFF4 58195968
#define OFF5 83361792
#define OFF6 83394560
#define OFF7 83402752
#define OFF8 83404800
#define OFF9 83404803
#define OFF10 83447843
#define OFF11 83447875
#define OFF12 83447908
#define OFF13 83447909

// scratch (allocation-free rule: __device__ globals; written every launch)
__device__ int g_sel0[32768], g_sel1[8192], g_sel2[2048];
__device__ int g_cnt[3];

__device__ __forceinline__ float4 zero4() { return make_float4(0.f, 0.f, 0.f, 0.f); }

// ---- Mask kernel: 32 blocks x 256 threads, no cross-block sync -----------
__global__ void __launch_bounds__(256)
mask_kernel(const float* __restrict__ imp1, const float* __restrict__ imp2,
            float* __restrict__ out) {
    const int b = blockIdx.x, tid = threadIdx.x;
    __shared__ unsigned char sm2all[2048];  // m2 bits, ALL batches
    __shared__ unsigned char sm1[256];      // m1 bits, own batch
    __shared__ int sC1[32], sC2[32];
    __shared__ unsigned short ssel0[1024], ssel1[256], ssel2[64];
    __shared__ int w0[8], w1[8], w2[8];
    __shared__ int sOff0, sOff1, sOff2;
    __shared__ int s_scu[33], s_sc0[32], s_sc01[32];

    // ---- A: m2 bits for all batches --------------------------------------
#pragma unroll
    for (int k = 0; k < 8; k++) {
        int i = tid + k * 256;
        sm2all[i] = imp2[i] < 0.3f;
    }
    __syncthreads();

    // ---- B: per-batch c1/c2 counts, all batches (8 threads per batch) ----
    {
        const int bb = tid >> 3, g = tid & 7;
        int c2p = 0;
#pragma unroll
        for (int k = 0; k < 8; k++) c2p += sm2all[bb * 64 + g * 8 + k];
        int c1p = 0;
#pragma unroll
        for (int k = 0; k < 32; k++) {
            int j = g * 32 + k;
            int r = j >> 4, c = j & 15;
            unsigned char cov2 = sm2all[bb * 64 + ((r >> 1) << 3) + (c >> 1)];
            c1p += (imp1[bb * 256 + j] < 0.5f) && !cov2;
        }
#pragma unroll
        for (int o = 4; o; o >>= 1) {
            c2p += __shfl_down_sync(0xffffffffu, c2p, o);
            c1p += __shfl_down_sync(0xffffffffu, c1p, o);
        }
        if (g == 0) { sC1[bb] = c1p; sC2[bb] = c2p; }
    }
    __syncthreads();

    // ---- C: local stitch scan (warp 0) -----------------------------------
    if (tid < 32) {
        int c1 = sC1[tid], c2 = sC2[tid];
        int c0 = 1024 - 16 * c2 - 4 * c1;
        int sl = 1 + c0 + c1 + c2;
        int x0 = c0, x1 = c1, x2 = c2, xs = sl;
#pragma unroll
        for (int o = 1; o < 32; o <<= 1) {
            int n0 = __shfl_up_sync(0xffffffffu, x0, o);
            int n1 = __shfl_up_sync(0xffffffffu, x1, o);
            int n2 = __shfl_up_sync(0xffffffffu, x2, o);
            int ns = __shfl_up_sync(0xffffffffu, xs, o);
            if (tid >= o) { x0 += n0; x1 += n1; x2 += n2; xs += ns; }
        }
        if (tid == b) { sOff0 = x0 - c0; sOff1 = x1 - c1; sOff2 = x2 - c2; }
        s_scu[tid + 1] = xs;
        s_sc0[tid] = c0;
        s_sc01[tid] = c0 + c1;
        if (tid == 0) s_scu[0] = 0;
        if (b == 0) {
            out[OFF10 + tid] = (float)sl;
            out[OFF11 + 1 + tid] = (float)xs;
            int mx = sl;
#pragma unroll
            for (int o = 16; o; o >>= 1) {
                int n = __shfl_xor_sync(0xffffffffu, mx, o);
                mx = mx > n ? mx : n;
            }
            if (tid == 0) {
                out[OFF11] = 0.0f;
                out[OFF12] = (float)mx;
            }
            if (tid == 31) {
                g_cnt[0] = x0; g_cnt[1] = x1; g_cnt[2] = x2;
                out[OFF8 + 0] = (float)x0;
                out[OFF8 + 1] = (float)x1;
                out[OFF8 + 2] = (float)x2;
                out[OFF13] = (float)xs / 32768.0f;
            }
        }
    }
    __syncthreads();

    // ---- D: own-batch masks + compaction ---------------------------------
    unsigned char v2 = 0;
    if (tid < 64) {
        v2 = sm2all[b * 64 + tid];
        out[OFF7 + b * 64 + tid] = (float)v2;
    }
    unsigned char v1;
    {
        int r = tid >> 4, c = tid & 15;
        unsigned char cov2 = sm2all[b * 64 + ((r >> 1) << 3) + (c >> 1)];
        v1 = (imp1[b * 256 + tid] < 0.5f) && !cov2;
        sm1[tid] = v1;
        out[OFF6 + b * 256 + tid] = (float)v1;
    }
    __syncthreads();

    unsigned char v0[4];
#pragma unroll
    for (int k = 0; k < 4; k++) {
        int j = tid * 4 + k;
        int r = j >> 5, c = j & 31;
        unsigned char cov = sm2all[b * 64 + ((r >> 2) << 3) + (c >> 2)] |
                            sm1[((r >> 1) << 4) + (c >> 1)];
        v0[k] = !cov;
        out[OFF5 + b * 1024 + j] = (float)v0[k];
    }

    const int lane = tid & 31, wid = tid >> 5;
    int s0 = v0[0] + v0[1] + v0[2] + v0[3];
    int a1 = (int)v1, a2 = (tid < 64) ? (int)v2 : 0;
    int i0 = s0, i1 = a1, i2 = a2;
#pragma unroll
    for (int o = 1; o < 32; o <<= 1) {
        int n0 = __shfl_up_sync(0xffffffffu, i0, o);
        int n1 = __shfl_up_sync(0xffffffffu, i1, o);
        int n2 = __shfl_up_sync(0xffffffffu, i2, o);
        if (lane >= o) { i0 += n0; i1 += n1; i2 += n2; }
    }
    if (lane == 31) { w0[wid] = i0; w1[wid] = i1; w2[wid] = i2; }
    __syncthreads();
    int base0 = 0, base1 = 0, base2 = 0, tot0 = 0, tot1 = 0, tot2 = 0;
#pragma unroll
    for (int k = 0; k < 8; k++) {
        if (k < wid) { base0 += w0[k]; base1 += w1[k]; base2 += w2[k]; }
        tot0 += w0[k]; tot1 += w1[k]; tot2 += w2[k];
    }
    {
        int r = base0 + i0 - s0;
#pragma unroll
        for (int k = 0; k < 4; k++)
            if (v0[k]) ssel0[r++] = (unsigned short)(tid * 4 + k);
    }
    if (v1) ssel1[base1 + i1 - a1] = (unsigned short)tid;
    if (tid < 64 && v2) ssel2[base2 + i2 - a2] = (unsigned short)tid;
    __syncthreads();

    // ---- global sel entries for own batch --------------------------------
    for (int r = tid; r < tot0; r += 256)
        g_sel0[sOff0 + r] = (int)ssel0[r] + (b << 10);
    for (int r = tid; r < tot1; r += 256)
        g_sel1[sOff1 + r] = (int)ssel1[r] + (b << 8);
    for (int r = tid; r < tot2; r += 256)
        g_sel2[sOff2 + r] = (int)ssel2[r] + (b << 6);

    // ---- E: this block's slice of compacted output_mask ------------------
    const int tot = s_scu[32];
    for (int j = b * 1345 + tid; j < (b + 1) * 1345; j += 256) {
        float v = 0.0f;
        if (j < tot) {
            int bb = 0;
            while (s_scu[bb + 1] <= j) bb++;
            int r = j - s_scu[bb];
            if (r == 0) v = -1.0f;
            else {
                r -= 1;
                if (r < s_sc0[bb]) v = 1.0f;
                else if (r < s_sc01[bb]) v = 2.0f;
                else v = 3.0f;
            }
        }
        out[OFF9 + j] = v;
    }
}

// ---------------------------------------------------------------------------
// Mega kernel: five big gather sections (proven R6 code, S5 removed)
// ---------------------------------------------------------------------------
#define NB0 3072
#define NB1 3072
#define NB2 1536
#define NB3 3072
#define NB4 3072
#define E0 (NB0)
#define E1 (NB0 + NB1)
#define E2 (NB0 + NB1 + NB2)
#define E3 (NB0 + NB1 + NB2 + NB3)
#define E4 (NB0 + NB1 + NB2 + NB3 + NB4)   // 13824

__global__ void __launch_bounds__(256)
mega_kernel(const float* __restrict__ img, float* __restrict__ out) {
    const int bs = blockIdx.x;
    const int tid = threadIdx.x;

    if (bs < E0) {
        // ---- S0: resized0 (pure copy of 16x16 base patches) --------------
        const int cnt = g_cnt[0];
        const int base = bs * 2048 + tid;
        int off[8];
#pragma unroll
        for (int k = 0; k < 8; k++) {
            int i = base + k * 256;
            int p = i / 192, t4 = i - p * 192;
            if (p < cnt) {
                int s = g_sel0[p];
                int b = s >> 10, gy = (s >> 5) & 31, gx = s & 31;
                int e = t4 << 2;
                int c = e >> 8, y = (e >> 4) & 15, x = e & 15;
                off[k] = ((b * 3 + c) * 512 + gy * 16 + y) * 512 + gx * 16 + x;
            } else off[k] = -1;
        }
        float4 v[8];
#pragma unroll
        for (int k = 0; k < 8; k++)
            v[k] = (off[k] >= 0) ? *reinterpret_cast<const float4*>(img + off[k]) : zero4();
        float4* dst = reinterpret_cast<float4*>(out);
#pragma unroll
        for (int k = 0; k < 8; k++) dst[base + k * 256] = v[k];

    } else if (bs < E1) {
        // ---- S1: resized1 (2x2 average of original) -----------------------
        const int cnt = g_cnt[1];
        const int base = (bs - E0) * 512 + tid;
        int off[2];
#pragma unroll
        for (int k = 0; k < 2; k++) {
            int i = base + k * 256;
            int p = i / 192, t4 = i - p * 192;
            if (p < cnt) {
                int s = g_sel1[p];
                int b = s >> 8, gy = (s >> 4) & 15, gx = s & 15;
                int e = t4 << 2;
                int c = e >> 8, y = (e >> 4) & 15, x = e & 15;
                int R = gy * 32 + 2 * y, Cc = gx * 32 + 2 * x;
                off[k] = ((b * 3 + c) * 512 + R) * 512 + Cc;
            } else off[k] = -1;
        }
        float4 a0[2], a1[2], b0[2], b1[2];
#pragma unroll
        for (int k = 0; k < 2; k++) {
            if (off[k] >= 0) {
                const float* bp = img + off[k];
                a0[k] = *(const float4*)(bp);
                a1[k] = *(const float4*)(bp + 4);
                b0[k] = *(const float4*)(bp + 512);
                b1[k] = *(const float4*)(bp + 516);
            }
        }
        float4* dst = reinterpret_cast<float4*>(out + OFF1);
#pragma unroll
        for (int k = 0; k < 2; k++) {
            float4 o = zero4();
            if (off[k] >= 0) {
                o.x = (a0[k].x + a0[k].y + b0[k].x + b0[k].y) * 0.25f;
                o.y = (a0[k].z + a0[k].w + b0[k].z + b0[k].w) * 0.25f;
                o.z = (a1[k].x + a1[k].y + b1[k].x + b1[k].y) * 0.25f;
                o.w = (a1[k].z + a1[k].w + b1[k].z + b1[k].w) * 0.25f;
            }
            dst[base + k * 256] = o;
        }

    } else if (bs < E2) {
        // ---- S2: resized2 (central 2x2 average, 4x downsample) ------------
        const int cnt = g_cnt[2];
        const int i = (bs - E1) * 256 + tid;
        const int p = i / 192, t4 = i - p * 192;
        float4 o = zero4();
        if (p < cnt) {
            int s = g_sel2[p];
            int b = s >> 6, gy = (s >> 3) & 7, gx = s & 7;
            int e = t4 << 2;
            int c = e >> 8, y = (e >> 4) & 15, x = e & 15;
            int R0 = gy * 64 + 4 * y + 1;
            int Cb = gx * 64 + 4 * x;
            const float* r0 = img + ((b * 3 + c) * 512 + R0) * 512 + Cb;
            const float* r1 = r0 + 512;
            float4 q0 = *(const float4*)r0, q1 = *(const float4*)(r0 + 4);
            float4 q2 = *(const float4*)(r0 + 8), q3 = *(const float4*)(r0 + 12);
            float4 u0 = *(const float4*)r1, u1 = *(const float4*)(r1 + 4);
            float4 u2 = *(const float4*)(r1 + 8), u3 = *(const float4*)(r1 + 12);
            o.x = (q0.y + q0.z + u0.y + u0.z) * 0.25f;
            o.y = (q1.y + q1.z + u1.y + u1.z) * 0.25f;
            o.z = (q2.y + q2.z + u2.y + u2.z) * 0.25f;
            o.w = (q3.y + q3.z + u3.y + u3.z) * 0.25f;
        }
        reinterpret_cast<float4*>(out + OFF2)[i] = o;

    } else if (bs < E3) {
        // ---- S3: fulls0 (2x2 constituent base patches, pure copy) ---------
        const int cnt = g_cnt[1];
        const int base = (bs - E2) * 2048 + tid;
        int off[8];
#pragma unroll
        for (int k = 0; k < 8; k++) {
            int i = base + k * 256;
            int p = i / 768, rf = i - p * 768;
            if (p < cnt) {
                int s = g_sel1[p];
                int b = s >> 8, gy = (s >> 4) & 15, gx = s & 15;
                int e = rf << 2;
                int sub = e / 768, rem = e - sub * 768;
                int c = rem >> 8, y = (rem >> 4) & 15, x = rem & 15;
                int ny = sub >> 1, nx = sub & 1;
                int R = gy * 32 + ny * 16 + y, Cc = gx * 32 + nx * 16 + x;
                off[k] = ((b * 3 + c) * 512 + R) * 512 + Cc;
            } else off[k] = -1;
        }
        float4 v[8];
#pragma unroll
        for (int k = 0; k < 8; k++)
            v[k] = (off[k] >= 0) ? *reinterpret_cast<const float4*>(img + off[k]) : zero4();
        float4* dst = reinterpret_cast<float4*>(out + OFF3);
#pragma unroll
        for (int k = 0; k < 8; k++) dst[base + k * 256] = v[k];

    } else {
        // ---- S4: fulls1 (4x4 constituent base patches, pure copy) ---------
        const int cnt = g_cnt[2];
        const int base = (bs - E3) * 2048 + tid;
        int off[8];
#pragma unroll
        for (int k = 0; k < 8; k++) {
            int i = base + k * 256;
            int p = i / 3072, rf = i - p * 3072;
            if (p < cnt) {
                int s = g_sel2[p];
                int b = s >> 6, gy = (s >> 3) & 7, gx = s & 7;
                int e = rf << 2;
                int sub = e / 768, rem = e - sub * 768;
                int c = rem >> 8, y = (rem >> 4) & 15, x = rem & 15;
                int ny = sub >> 2, nx = sub & 3;
                int R = gy * 64 + ny * 16 + y, Cc = gx * 64 + nx * 16 + x;
                off[k] = ((b * 3 + c) * 512 + R) * 512 + Cc;
            } else off[k] = -1;
        }
        float4 v[8];
#pragma unroll
        for (int k = 0; k < 8; k++)
            v[k] = (off[k] >= 0) ? *reinterpret_cast<const float4*>(img + off[k]) : zero4();
        float4* dst = reinterpret_cast<float4*>(out + OFF4);
#pragma unroll
        for (int k = 0; k < 8; k++) dst[base + k * 256] = v[k];
    }
}

extern "C" void kernel_launch(void* const* d_in, const int* in_sizes, int n_in,
                              void* d_out, int out_size) {
    const float* img = (const float*)d_in[0];   // images  (32,3,512,512)
    const float* i1  = (const float*)d_in[2];   // imp_s1  (32,16,16)
    const float* i2  = (const float*)d_in[3];   // imp_s2  (32,8,8)
    float* out = (float*)d_out;

    mask_kernel<<<32, 256>>>(i1, i2, out);
    mega_kernel<<<E4, 256>>>(img, out);
}

// round 10
// speedup vs baseline: 1.2465x; 1.0974x over previous
#include <cuda_runtime.h>

// ---------------------------------------------------------------------------
// PatchTokenizer: hierarchical mask selection + compacted patch gathers.
//   mask_kernel (32 blocks): R6 spin-stitch version + per-batch output_mask
//   mega_kernel (13824 blocks): proven gather sections (R9, no S5)
// ---------------------------------------------------------------------------

#define OFF1 25165824
#define OFF2 31457280
#define OFF3 33030144
#define OFF4 58195968
#define OFF5 83361792
#define OFF6 83394560
#define OFF7 83402752
#define OFF8 83404800
#define OFF9 83404803
#define OFF10 83447843
#define OFF11 83447875
#define OFF12 83447908
#define OFF13 83447909

// scratch (allocation-free rule: __device__ globals)
__device__ int g_c0[32], g_c1[32], g_c2[32];
__device__ int g_sel0[32768], g_sel1[8192], g_sel2[2048];
__device__ int g_cnt[3];
__device__ int g_ready;  // zero-init; reset by mega_kernel block 0 each launch

__device__ __forceinline__ float4 zero4() { return make_float4(0.f, 0.f, 0.f, 0.f); }

// ---- Mask kernel: 32 blocks x 256 threads, spin barrier + dist. stitch ---
__global__ void __launch_bounds__(256)
mask_kernel(const float* __restrict__ imp1, const float* __restrict__ imp2,
            float* __restrict__ out) {
    const int b = blockIdx.x, tid = threadIdx.x;
    __shared__ unsigned char sm2[64], sm1[256];
    __shared__ unsigned short ssel0[1024], ssel1[256], ssel2[64];
    __shared__ int w0[8], w1[8], w2[8];
    __shared__ int sOff0, sOff1, sOff2, sStart, sTotAll;

    // ---- phase 1: per-batch masks ----------------------------------------
    unsigned char v2 = 0;
    if (tid < 64) {
        v2 = imp2[b * 64 + tid] < 0.3f;
        sm2[tid] = v2;
        out[OFF7 + b * 64 + tid] = (float)v2;
    }
    __syncthreads();

    unsigned char v1;
    {
        int r = tid >> 4, c = tid & 15;
        unsigned char cov2 = sm2[((r >> 1) << 3) + (c >> 1)];
        v1 = (imp1[b * 256 + tid] < 0.5f) && !cov2;
        sm1[tid] = v1;
        out[OFF6 + b * 256 + tid] = (float)v1;
    }
    __syncthreads();

    unsigned char v0[4];
#pragma unroll
    for (int k = 0; k < 4; k++) {
        int j = tid * 4 + k;
        int r = j >> 5, c = j & 31;
        unsigned char cov = sm2[((r >> 2) << 3) + (c >> 2)] |
                            sm1[((r >> 1) << 4) + (c >> 1)];
        v0[k] = !cov;
        out[OFF5 + b * 1024 + j] = (float)v0[k];
    }

    // ---- local compaction scans -> shared sel lists ----------------------
    const int lane = tid & 31, wid = tid >> 5;
    int s0 = v0[0] + v0[1] + v0[2] + v0[3];
    int a1 = (int)v1, a2 = (tid < 64) ? (int)v2 : 0;
    int i0 = s0, i1 = a1, i2 = a2;
#pragma unroll
    for (int o = 1; o < 32; o <<= 1) {
        int n0 = __shfl_up_sync(0xffffffffu, i0, o);
        int n1 = __shfl_up_sync(0xffffffffu, i1, o);
        int n2 = __shfl_up_sync(0xffffffffu, i2, o);
        if (lane >= o) { i0 += n0; i1 += n1; i2 += n2; }
    }
    if (lane == 31) { w0[wid] = i0; w1[wid] = i1; w2[wid] = i2; }
    __syncthreads();
    int base0 = 0, base1 = 0, base2 = 0, tot0 = 0, tot1 = 0, tot2 = 0;
#pragma unroll
    for (int k = 0; k < 8; k++) {
        if (k < wid) { base0 += w0[k]; base1 += w1[k]; base2 += w2[k]; }
        tot0 += w0[k]; tot1 += w1[k]; tot2 += w2[k];
    }
    {
        int r = base0 + i0 - s0;
#pragma unroll
        for (int k = 0; k < 4; k++)
            if (v0[k]) ssel0[r++] = (unsigned short)(tid * 4 + k);
    }
    if (v1) ssel1[base1 + i1 - a1] = (unsigned short)tid;
    if (tid < 64 && v2) ssel2[base2 + i2 - a2] = (unsigned short)tid;

    if (tid == 0) {
        g_c0[b] = tot0; g_c1[b] = tot1; g_c2[b] = tot2;
        out[OFF10 + b] = (float)(1 + tot0 + tot1 + tot2);
    }
    __threadfence();
    __syncthreads();
    if (tid == 0) {
        atomicAdd(&g_ready, 1);
        while (atomicAdd(&g_ready, 0) < 32) {}
        __threadfence();
    }
    __syncthreads();
    __threadfence();

    // ---- distributed stitch: every block scans all 32 counts -------------
    if (tid < 32) {
        int c0 = g_c0[tid], c1 = g_c1[tid], c2 = g_c2[tid];
        int sl = 1 + c0 + c1 + c2;
        int x0 = c0, x1 = c1, x2 = c2, xs = sl;
#pragma unroll
        for (int o = 1; o < 32; o <<= 1) {
            int n0 = __shfl_up_sync(0xffffffffu, x0, o);
            int n1 = __shfl_up_sync(0xffffffffu, x1, o);
            int n2 = __shfl_up_sync(0xffffffffu, x2, o);
            int ns = __shfl_up_sync(0xffffffffu, xs, o);
            if (tid >= o) { x0 += n0; x1 += n1; x2 += n2; xs += ns; }
        }
        if (tid == b) {
            sOff0 = x0 - c0; sOff1 = x1 - c1; sOff2 = x2 - c2;
            sStart = xs - sl;
        }
        if (tid == 31) sTotAll = xs;
        if (b == 0) {
            out[OFF11 + 1 + tid] = (float)xs;
            int mx = sl;
#pragma unroll
            for (int o = 16; o; o >>= 1) {
                int n = __shfl_xor_sync(0xffffffffu, mx, o);
                mx = mx > n ? mx : n;
            }
            if (tid == 0) {
                out[OFF11] = 0.0f;
                out[OFF12] = (float)mx;
            }
            if (tid == 31) {
                g_cnt[0] = x0; g_cnt[1] = x1; g_cnt[2] = x2;
                out[OFF8 + 0] = (float)x0;
                out[OFF8 + 1] = (float)x1;
                out[OFF8 + 2] = (float)x2;
                out[OFF13] = (float)xs / 32768.0f;
            }
        }
    }
    __syncthreads();

    // ---- finalize this batch's global sel entries ------------------------
    for (int r = tid; r < tot0; r += 256)
        g_sel0[sOff0 + r] = (int)ssel0[r] + (b << 10);
    for (int r = tid; r < tot1; r += 256)
        g_sel1[sOff1 + r] = (int)ssel1[r] + (b << 8);
    for (int r = tid; r < tot2; r += 256)
        g_sel2[sOff2 + r] = (int)ssel2[r] + (b << 6);

    // ---- output_mask: own segment (no scan loop) + tail chunk ------------
    {
        const int seg = 1 + tot0 + tot1 + tot2;
        const int t01 = 1 + tot0;
        const int t012 = 1 + tot0 + tot1;
        for (int i = tid; i < seg; i += 256) {
            float v;
            if (i == 0) v = -1.0f;
            else if (i < t01) v = 1.0f;
            else if (i < t012) v = 2.0f;
            else v = 3.0f;
            out[OFF9 + sStart + i] = v;
        }
        const int tot = sTotAll;
        const int tail = 43040 - tot;
        const int chunk = (tail + 31) >> 5;
        const int lo = tot + b * chunk;
        int hi = lo + chunk;
        if (hi > 43040) hi = 43040;
        for (int j = lo + tid; j < hi; j += 256) out[OFF9 + j] = 0.0f;
    }
}

// ---------------------------------------------------------------------------
// Mega kernel: five big gather sections (proven, no S5)
// ---------------------------------------------------------------------------
#define NB0 3072
#define NB1 3072
#define NB2 1536
#define NB3 3072
#define NB4 3072
#define E0 (NB0)
#define E1 (NB0 + NB1)
#define E2 (NB0 + NB1 + NB2)
#define E3 (NB0 + NB1 + NB2 + NB3)
#define E4 (NB0 + NB1 + NB2 + NB3 + NB4)   // 13824

__global__ void __launch_bounds__(256)
mega_kernel(const float* __restrict__ img, float* __restrict__ out) {
    const int bs = blockIdx.x;
    const int tid = threadIdx.x;

    if (bs == 0 && tid == 0) g_ready = 0;  // stream-ordered reset for next run

    if (bs < E0) {
        // ---- S0: resized0 (pure copy of 16x16 base patches) --------------
        const int cnt = g_cnt[0];
        const int base = bs * 2048 + tid;
        int off[8];
#pragma unroll
        for (int k = 0; k < 8; k++) {
            int i = base + k * 256;
            int p = i / 192, t4 = i - p * 192;
            if (p < cnt) {
                int s = g_sel0[p];
                int b = s >> 10, gy = (s >> 5) & 31, gx = s & 31;
                int e = t4 << 2;
                int c = e >> 8, y = (e >> 4) & 15, x = e & 15;
                off[k] = ((b * 3 + c) * 512 + gy * 16 + y) * 512 + gx * 16 + x;
            } else off[k] = -1;
        }
        float4 v[8];
#pragma unroll
        for (int k = 0; k < 8; k++)
            v[k] = (off[k] >= 0) ? *reinterpret_cast<const float4*>(img + off[k]) : zero4();
        float4* dst = reinterpret_cast<float4*>(out);
#pragma unroll
        for (int k = 0; k < 8; k++) dst[base + k * 256] = v[k];

    } else if (bs < E1) {
        // ---- S1: resized1 (2x2 average of original) -----------------------
        const int cnt = g_cnt[1];
        const int base = (bs - E0) * 512 + tid;
        int off[2];
#pragma unroll
        for (int k = 0; k < 2; k++) {
            int i = base + k * 256;
            int p = i / 192, t4 = i - p * 192;
            if (p < cnt) {
                int s = g_sel1[p];
                int b = s >> 8, gy = (s >> 4) & 15, gx = s & 15;
                int e = t4 << 2;
                int c = e >> 8, y = (e >> 4) & 15, x = e & 15;
                int R = gy * 32 + 2 * y, Cc = gx * 32 + 2 * x;
                off[k] = ((b * 3 + c) * 512 + R) * 512 + Cc;
            } else off[k] = -1;
        }
        float4 a0[2], a1[2], b0[2], b1[2];
#pragma unroll
        for (int k = 0; k < 2; k++) {
            if (off[k] >= 0) {
                const float* bp = img + off[k];
                a0[k] = *(const float4*)(bp);
                a1[k] = *(const float4*)(bp + 4);
                b0[k] = *(const float4*)(bp + 512);
                b1[k] = *(const float4*)(bp + 516);
            }
        }
        float4* dst = reinterpret_cast<float4*>(out + OFF1);
#pragma unroll
        for (int k = 0; k < 2; k++) {
            float4 o = zero4();
            if (off[k] >= 0) {
                o.x = (a0[k].x + a0[k].y + b0[k].x + b0[k].y) * 0.25f;
                o.y = (a0[k].z + a0[k].w + b0[k].z + b0[k].w) * 0.25f;
                o.z = (a1[k].x + a1[k].y + b1[k].x + b1[k].y) * 0.25f;
                o.w = (a1[k].z + a1[k].w + b1[k].z + b1[k].w) * 0.25f;
            }
            dst[base + k * 256] = o;
        }

    } else if (bs < E2) {
        // ---- S2: resized2 (central 2x2 average, 4x downsample) ------------
        const int cnt = g_cnt[2];
        const int i = (bs - E1) * 256 + tid;
        const int p = i / 192, t4 = i - p * 192;
        float4 o = zero4();
        if (p < cnt) {
            int s = g_sel2[p];
            int b = s >> 6, gy = (s >> 3) & 7, gx = s & 7;
            int e = t4 << 2;
            int c = e >> 8, y = (e >> 4) & 15, x = e & 15;
            int R0 = gy * 64 + 4 * y + 1;
            int Cb = gx * 64 + 4 * x;
            const float* r0 = img + ((b * 3 + c) * 512 + R0) * 512 + Cb;
            const float* r1 = r0 + 512;
            float4 q0 = *(const float4*)r0, q1 = *(const float4*)(r0 + 4);
            float4 q2 = *(const float4*)(r0 + 8), q3 = *(const float4*)(r0 + 12);
            float4 u0 = *(const float4*)r1, u1 = *(const float4*)(r1 + 4);
            float4 u2 = *(const float4*)(r1 + 8), u3 = *(const float4*)(r1 + 12);
            o.x = (q0.y + q0.z + u0.y + u0.z) * 0.25f;
            o.y = (q1.y + q1.z + u1.y + u1.z) * 0.25f;
            o.z = (q2.y + q2.z + u2.y + u2.z) * 0.25f;
            o.w = (q3.y + q3.z + u3.y + u3.z) * 0.25f;
        }
        reinterpret_cast<float4*>(out + OFF2)[i] = o;

    } else if (bs < E3) {
        // ---- S3: fulls0 (2x2 constituent base patches, pure copy) ---------
        const int cnt = g_cnt[1];
        const int base = (bs - E2) * 2048 + tid;
        int off[8];
#pragma unroll
        for (int k = 0; k < 8; k++) {
            int i = base + k * 256;
            int p = i / 768, rf = i - p * 768;
            if (p < cnt) {
                int s = g_sel1[p];
                int b = s >> 8, gy = (s >> 4) & 15, gx = s & 15;
                int e = rf << 2;
                int sub = e / 768, rem = e - sub * 768;
                int c = rem >> 8, y = (rem >> 4) & 15, x = rem & 15;
                int ny = sub >> 1, nx = sub & 1;
                int R = gy * 32 + ny * 16 + y, Cc = gx * 32 + nx * 16 + x;
                off[k] = ((b * 3 + c) * 512 + R) * 512 + Cc;
            } else off[k] = -1;
        }
        float4 v[8];
#pragma unroll
        for (int k = 0; k < 8; k++)
            v[k] = (off[k] >= 0) ? *reinterpret_cast<const float4*>(img + off[k]) : zero4();
        float4* dst = reinterpret_cast<float4*>(out + OFF3);
#pragma unroll
        for (int k = 0; k < 8; k++) dst[base + k * 256] = v[k];

    } else {
        // ---- S4: fulls1 (4x4 constituent base patches, pure copy) ---------
        const int cnt = g_cnt[2];
        const int base = (bs - E3) * 2048 + tid;
        int off[8];
#pragma unroll
        for (int k = 0; k < 8; k++) {
            int i = base + k * 256;
            int p = i / 3072, rf = i - p * 3072;
            if (p < cnt) {
                int s = g_sel2[p];
                int b = s >> 6, gy = (s >> 3) & 7, gx = s & 7;
                int e = rf << 2;
                int sub = e / 768, rem = e - sub * 768;
                int c = rem >> 8, y = (rem >> 4) & 15, x = rem & 15;
                int ny = sub >> 2, nx = sub & 3;
                int R = gy * 64 + ny * 16 + y, Cc = gx * 64 + nx * 16 + x;
                off[k] = ((b * 3 + c) * 512 + R) * 512 + Cc;
            } else off[k] = -1;
        }
        float4 v[8];
#pragma unroll
        for (int k = 0; k < 8; k++)
            v[k] = (off[k] >= 0) ? *reinterpret_cast<const float4*>(img + off[k]) : zero4();
        float4* dst = reinterpret_cast<float4*>(out + OFF4);
#pragma unroll
        for (int k = 0; k < 8; k++) dst[base + k * 256] = v[k];
    }
}

extern "C" void kernel_launch(void* const* d_in, const int* in_sizes, int n_in,
                              void* d_out, int out_size) {
    const float* img = (const float*)d_in[0];   // images  (32,3,512,512)
    const float* i1  = (const float*)d_in[2];   // imp_s1  (32,16,16)
    const float* i2  = (const float*)d_in[3];   // imp_s2  (32,8,8)
    float* out = (float*)d_out;

    mask_kernel<<<32, 256>>>(i1, i2, out);
    mega_kernel<<<E4, 256>>>(img, out);
}

// round 11
// speedup vs baseline: 1.2504x; 1.0031x over previous
#include <cuda_runtime.h>

// ---------------------------------------------------------------------------
// PatchTokenizer: hierarchical mask selection + compacted patch gathers.
//   mask_kernel (32 blocks): barrier-free — every block redundantly counts
//     all batches with COALESCED imp reads (c0 = 1024-16*c2-4*c1), derives
//     global offsets locally; own-batch compaction + output_mask segment.
//   mega_kernel (13824 blocks): proven gather sections (unchanged).
// ---------------------------------------------------------------------------

#define OFF1 25165824
#define OFF2 31457280
#define OFF3 33030144
#define OFF4 58195968
#define OFF5 83361792
#define OFF6 83394560
#define OFF7 83402752
#define OFF8 83404800
#define OFF9 83404803
#define OFF10 83447843
#define OFF11 83447875
#define OFF12 83447908
#define OFF13 83447909

// scratch (allocation-free rule: __device__ globals; rewritten every launch)
__device__ int g_sel0[32768], g_sel1[8192], g_sel2[2048];
__device__ int g_cnt[3];

__device__ __forceinline__ float4 zero4() { return make_float4(0.f, 0.f, 0.f, 0.f); }

// ---- Mask kernel: 32 blocks x 256 threads, no cross-block sync -----------
__global__ void __launch_bounds__(256)
mask_kernel(const float* __restrict__ imp1, const float* __restrict__ imp2,
            float* __restrict__ out) {
    const int b = blockIdx.x, tid = threadIdx.x;
    __shared__ unsigned char sm2all[2048];  // m2 bits, ALL batches
    __shared__ unsigned char sm1[256];      // m1 bits, own batch
    __shared__ int sC1[32], sC2[32];
    __shared__ unsigned short ssel0[1024], ssel1[256], ssel2[64];
    __shared__ int w0[8], w1[8], w2[8];
    __shared__ int sOff0, sOff1, sOff2, sStart, sTotAll;

    // ---- A: m2 bits for all batches (coalesced) --------------------------
#pragma unroll
    for (int k = 0; k < 8; k++) {
        int i = tid + k * 256;
        sm2all[i] = imp2[i] < 0.3f;
    }
    __syncthreads();

    // ---- B: per-batch c1/c2 counts, all batches, COALESCED ----------------
    // warp w handles batches 4w..4w+3; lane l reads imp1[bb*256 + k*32 + l]
    {
        const int w = tid >> 5, l = tid & 31;
#pragma unroll
        for (int q = 0; q < 4; q++) {
            int bb = w * 4 + q;
            int c2p = (int)sm2all[bb * 64 + l] + (int)sm2all[bb * 64 + 32 + l];
            int c1p = 0;
#pragma unroll
            for (int k = 0; k < 8; k++) {
                int j = k * 32 + l;
                int r = j >> 4, c = j & 15;
                unsigned char cov2 = sm2all[bb * 64 + ((r >> 1) << 3) + (c >> 1)];
                c1p += (imp1[bb * 256 + j] < 0.5f) && !cov2;
            }
#pragma unroll
            for (int o = 16; o; o >>= 1) {
                c2p += __shfl_down_sync(0xffffffffu, c2p, o);
                c1p += __shfl_down_sync(0xffffffffu, c1p, o);
            }
            if (l == 0) { sC1[bb] = c1p; sC2[bb] = c2p; }
        }
    }
    __syncthreads();

    // ---- C: local stitch scan (warp 0; c0 derived analytically) -----------
    if (tid < 32) {
        int c1 = sC1[tid], c2 = sC2[tid];
        int c0 = 1024 - 16 * c2 - 4 * c1;
        int sl = 1 + c0 + c1 + c2;
        int x0 = c0, x1 = c1, x2 = c2, xs = sl;
#pragma unroll
        for (int o = 1; o < 32; o <<= 1) {
            int n0 = __shfl_up_sync(0xffffffffu, x0, o);
            int n1 = __shfl_up_sync(0xffffffffu, x1, o);
            int n2 = __shfl_up_sync(0xffffffffu, x2, o);
            int ns = __shfl_up_sync(0xffffffffu, xs, o);
            if (tid >= o) { x0 += n0; x1 += n1; x2 += n2; xs += ns; }
        }
        if (tid == b) {
            sOff0 = x0 - c0; sOff1 = x1 - c1; sOff2 = x2 - c2;
            sStart = xs - sl;
        }
        if (tid == 31) sTotAll = xs;
        if (b == 0) {
            out[OFF10 + tid] = (float)sl;
            out[OFF11 + 1 + tid] = (float)xs;
            int mx = sl;
#pragma unroll
            for (int o = 16; o; o >>= 1) {
                int n = __shfl_xor_sync(0xffffffffu, mx, o);
                mx = mx > n ? mx : n;
            }
            if (tid == 0) {
                out[OFF11] = 0.0f;
                out[OFF12] = (float)mx;
            }
            if (tid == 31) {
                g_cnt[0] = x0; g_cnt[1] = x1; g_cnt[2] = x2;
                out[OFF8 + 0] = (float)x0;
                out[OFF8 + 1] = (float)x1;
                out[OFF8 + 2] = (float)x2;
                out[OFF13] = (float)xs / 32768.0f;
            }
        }
    }
    __syncthreads();

    // ---- D: own-batch masks + compaction (proven R10 path) ---------------
    unsigned char v2 = 0;
    if (tid < 64) {
        v2 = sm2all[b * 64 + tid];
        out[OFF7 + b * 64 + tid] = (float)v2;
    }
    unsigned char v1;
    {
        int r = tid >> 4, c = tid & 15;
        unsigned char cov2 = sm2all[b * 64 + ((r >> 1) << 3) + (c >> 1)];
        v1 = (imp1[b * 256 + tid] < 0.5f) && !cov2;
        sm1[tid] = v1;
        out[OFF6 + b * 256 + tid] = (float)v1;
    }
    __syncthreads();

    unsigned char v0[4];
#pragma unroll
    for (int k = 0; k < 4; k++) {
        int j = tid * 4 + k;
        int r = j >> 5, c = j & 31;
        unsigned char cov = sm2all[b * 64 + ((r >> 2) << 3) + (c >> 2)] |
                            sm1[((r >> 1) << 4) + (c >> 1)];
        v0[k] = !cov;
        out[OFF5 + b * 1024 + j] = (float)v0[k];
    }

    const int lane = tid & 31, wid = tid >> 5;
    int s0 = v0[0] + v0[1] + v0[2] + v0[3];
    int a1 = (int)v1, a2 = (tid < 64) ? (int)v2 : 0;
    int i0 = s0, i1 = a1, i2 = a2;
#pragma unroll
    for (int o = 1; o < 32; o <<= 1) {
        int n0 = __shfl_up_sync(0xffffffffu, i0, o);
        int n1 = __shfl_up_sync(0xffffffffu, i1, o);
        int n2 = __shfl_up_sync(0xffffffffu, i2, o);
        if (lane >= o) { i0 += n0; i1 += n1; i2 += n2; }
    }
    if (lane == 31) { w0[wid] = i0; w1[wid] = i1; w2[wid] = i2; }
    __syncthreads();
    int base0 = 0, base1 = 0, base2 = 0, tot0 = 0, tot1 = 0, tot2 = 0;
#pragma unroll
    for (int k = 0; k < 8; k++) {
        if (k < wid) { base0 += w0[k]; base1 += w1[k]; base2 += w2[k]; }
        tot0 += w0[k]; tot1 += w1[k]; tot2 += w2[k];
    }
    {
        int r = base0 + i0 - s0;
#pragma unroll
        for (int k = 0; k < 4; k++)
            if (v0[k]) ssel0[r++] = (unsigned short)(tid * 4 + k);
    }
    if (v1) ssel1[base1 + i1 - a1] = (unsigned short)tid;
    if (tid < 64 && v2) ssel2[base2 + i2 - a2] = (unsigned short)tid;
    __syncthreads();

    // ---- global sel entries for own batch --------------------------------
    for (int r = tid; r < tot0; r += 256)
        g_sel0[sOff0 + r] = (int)ssel0[r] + (b << 10);
    for (int r = tid; r < tot1; r += 256)
        g_sel1[sOff1 + r] = (int)ssel1[r] + (b << 8);
    for (int r = tid; r < tot2; r += 256)
        g_sel2[sOff2 + r] = (int)ssel2[r] + (b << 6);

    // ---- output_mask: own segment (range compare) + tail chunk ------------
    {
        const int seg = 1 + tot0 + tot1 + tot2;
        const int t01 = 1 + tot0;
        const int t012 = 1 + tot0 + tot1;
        for (int i = tid; i < seg; i += 256) {
            float v;
            if (i == 0) v = -1.0f;
            else if (i < t01) v = 1.0f;
            else if (i < t012) v = 2.0f;
            else v = 3.0f;
            out[OFF9 + sStart + i] = v;
        }
        const int tot = sTotAll;
        const int tail = 43040 - tot;
        const int chunk = (tail + 31) >> 5;
        const int lo = tot + b * chunk;
        int hi = lo + chunk;
        if (hi > 43040) hi = 43040;
        for (int j = lo + tid; j < hi; j += 256) out[OFF9 + j] = 0.0f;
    }
}

// ---------------------------------------------------------------------------
// Mega kernel: five big gather sections (proven, unchanged)
// ---------------------------------------------------------------------------
#define NB0 3072
#define NB1 3072
#define NB2 1536
#define NB3 3072
#define NB4 3072
#define E0 (NB0)
#define E1 (NB0 + NB1)
#define E2 (NB0 + NB1 + NB2)
#define E3 (NB0 + NB1 + NB2 + NB3)
#define E4 (NB0 + NB1 + NB2 + NB3 + NB4)   // 13824

__global__ void __launch_bounds__(256)
mega_kernel(const float* __restrict__ img, float* __restrict__ out) {
    const int bs = blockIdx.x;
    const int tid = threadIdx.x;

    if (bs < E0) {
        // ---- S0: resized0 (pure copy of 16x16 base patches) --------------
        const int cnt = g_cnt[0];
        const int base = bs * 2048 + tid;
        int off[8];
#pragma unroll
        for (int k = 0; k < 8; k++) {
            int i = base + k * 256;
            int p = i / 192, t4 = i - p * 192;
            if (p < cnt) {
                int s = g_sel0[p];
                int b = s >> 10, gy = (s >> 5) & 31, gx = s & 31;
                int e = t4 << 2;
                int c = e >> 8, y = (e >> 4) & 15, x = e & 15;
                off[k] = ((b * 3 + c) * 512 + gy * 16 + y) * 512 + gx * 16 + x;
            } else off[k] = -1;
        }
        float4 v[8];
#pragma unroll
        for (int k = 0; k < 8; k++)
            v[k] = (off[k] >= 0) ? *reinterpret_cast<const float4*>(img + off[k]) : zero4();
        float4* dst = reinterpret_cast<float4*>(out);
#pragma unroll
        for (int k = 0; k < 8; k++) dst[base + k * 256] = v[k];

    } else if (bs < E1) {
        // ---- S1: resized1 (2x2 average of original) -----------------------
        const int cnt = g_cnt[1];
        const int base = (bs - E0) * 512 + tid;
        int off[2];
#pragma unroll
        for (int k = 0; k < 2; k++) {
            int i = base + k * 256;
            int p = i / 192, t4 = i - p * 192;
            if (p < cnt) {
                int s = g_sel1[p];
                int b = s >> 8, gy = (s >> 4) & 15, gx = s & 15;
                int e = t4 << 2;
                int c = e >> 8, y = (e >> 4) & 15, x = e & 15;
                int R = gy * 32 + 2 * y, Cc = gx * 32 + 2 * x;
                off[k] = ((b * 3 + c) * 512 + R) * 512 + Cc;
            } else off[k] = -1;
        }
        float4 a0[2], a1[2], b0[2], b1[2];
#pragma unroll
        for (int k = 0; k < 2; k++) {
            if (off[k] >= 0) {
                const float* bp = img + off[k];
                a0[k] = *(const float4*)(bp);
                a1[k] = *(const float4*)(bp + 4);
                b0[k] = *(const float4*)(bp + 512);
                b1[k] = *(const float4*)(bp + 516);
            }
        }
        float4* dst = reinterpret_cast<float4*>(out + OFF1);
#pragma unroll
        for (int k = 0; k < 2; k++) {
            float4 o = zero4();
            if (off[k] >= 0) {
                o.x = (a0[k].x + a0[k].y + b0[k].x + b0[k].y) * 0.25f;
                o.y = (a0[k].z + a0[k].w + b0[k].z + b0[k].w) * 0.25f;
                o.z = (a1[k].x + a1[k].y + b1[k].x + b1[k].y) * 0.25f;
                o.w = (a1[k].z + a1[k].w + b1[k].z + b1[k].w) * 0.25f;
            }
            dst[base + k * 256] = o;
        }

    } else if (bs < E2) {
        // ---- S2: resized2 (central 2x2 average, 4x downsample) ------------
        const int cnt = g_cnt[2];
        const int i = (bs - E1) * 256 + tid;
        const int p = i / 192, t4 = i - p * 192;
        float4 o = zero4();
        if (p < cnt) {
            int s = g_sel2[p];
            int b = s >> 6, gy = (s >> 3) & 7, gx = s & 7;
            int e = t4 << 2;
            int c = e >> 8, y = (e >> 4) & 15, x = e & 15;
            int R0 = gy * 64 + 4 * y + 1;
            int Cb = gx * 64 + 4 * x;
            const float* r0 = img + ((b * 3 + c) * 512 + R0) * 512 + Cb;
            const float* r1 = r0 + 512;
            float4 q0 = *(const float4*)r0, q1 = *(const float4*)(r0 + 4);
            float4 q2 = *(const float4*)(r0 + 8), q3 = *(const float4*)(r0 + 12);
            float4 u0 = *(const float4*)r1, u1 = *(const float4*)(r1 + 4);
            float4 u2 = *(const float4*)(r1 + 8), u3 = *(const float4*)(r1 + 12);
            o.x = (q0.y + q0.z + u0.y + u0.z) * 0.25f;
            o.y = (q1.y + q1.z + u1.y + u1.z) * 0.25f;
            o.z = (q2.y + q2.z + u2.y + u2.z) * 0.25f;
            o.w = (q3.y + q3.z + u3.y + u3.z) * 0.25f;
        }
        reinterpret_cast<float4*>(out + OFF2)[i] = o;

    } else if (bs < E3) {
        // ---- S3: fulls0 (2x2 constituent base patches, pure copy) ---------
        const int cnt = g_cnt[1];
        const int base = (bs - E2) * 2048 + tid;
        int off[8];
#pragma unroll
        for (int k = 0; k < 8; k++) {
            int i = base + k * 256;
            int p = i / 768, rf = i - p * 768;
            if (p < cnt) {
                int s = g_sel1[p];
                int b = s >> 8, gy = (s >> 4) & 15, gx = s & 15;
                int e = rf << 2;
                int sub = e / 768, rem = e - sub * 768;
                int c = rem >> 8, y = (rem >> 4) & 15, x = rem & 15;
                int ny = sub >> 1, nx = sub & 1;
                int R = gy * 32 + ny * 16 + y, Cc = gx * 32 + nx * 16 + x;
                off[k] = ((b * 3 + c) * 512 + R) * 512 + Cc;
            } else off[k] = -1;
        }
        float4 v[8];
#pragma unroll
        for (int k = 0; k < 8; k++)
            v[k] = (off[k] >= 0) ? *reinterpret_cast<const float4*>(img + off[k]) : zero4();
        float4* dst = reinterpret_cast<float4*>(out + OFF3);
#pragma unroll
        for (int k = 0; k < 8; k++) dst[base + k * 256] = v[k];

    } else {
        // ---- S4: fulls1 (4x4 constituent base patches, pure copy) ---------
        const int cnt = g_cnt[2];
        const int base = (bs - E3) * 2048 + tid;
        int off[8];
#pragma unroll
        for (int k = 0; k < 8; k++) {
            int i = base + k * 256;
            int p = i / 3072, rf = i - p * 3072;
            if (p < cnt) {
                int s = g_sel2[p];
                int b = s >> 6, gy = (s >> 3) & 7, gx = s & 7;
                int e = rf << 2;
                int sub = e / 768, rem = e - sub * 768;
                int c = rem >> 8, y = (rem >> 4) & 15, x = rem & 15;
                int ny = sub >> 2, nx = sub & 3;
                int R = gy * 64 + ny * 16 + y, Cc = gx * 64 + nx * 16 + x;
                off[k] = ((b * 3 + c) * 512 + R) * 512 + Cc;
            } else off[k] = -1;
        }
        float4 v[8];
#pragma unroll
        for (int k = 0; k < 8; k++)
            v[k] = (off[k] >= 0) ? *reinterpret_cast<const float4*>(img + off[k]) : zero4();
        float4* dst = reinterpret_cast<float4*>(out + OFF4);
#pragma unroll
        for (int k = 0; k < 8; k++) dst[base + k * 256] = v[k];
    }
}

extern "C" void kernel_launch(void* const* d_in, const int* in_sizes, int n_in,
                              void* d_out, int out_size) {
    const float* img = (const float*)d_in[0];   // images  (32,3,512,512)
    const float* i1  = (const float*)d_in[2];   // imp_s1  (32,16,16)
    const float* i2  = (const float*)d_in[3];   // imp_s2  (32,8,8)
    float* out = (float*)d_out;

    mask_kernel<<<32, 256>>>(i1, i2, out);
    mega_kernel<<<E4, 256>>>(img, out);
}